// round 14
// baseline (speedup 1.0000x reference)
#include <cuda_runtime.h>
#include <cuda_fp16.h>
#include <math.h>

#define BATCH 2
#define NHEAD 16
#define SEQ   2048
#define EMB   1024
#define HDIM  64
#define GATE_EPS 1e-4f

typedef unsigned int u32;

// ------------------ scratch (all fp16 hi-only) ------------------
__device__ __half g_Xh[4096 * 1024];
__device__ __half g_Wh[4 * 1024 * 1024];
__device__ __half g_Qh[32 * 2048 * 64];
__device__ __half g_Kh[32 * 2048 * 64];
__device__ __half g_Vh[32 * 64 * 2048];
__device__ __half g_Ch[4096 * 1024];

// ------------------------------- helpers ---------------------------------------
__device__ __forceinline__ u32 pack_half2(float x, float y) {
    __half2 hp = __halves2half2(__float2half(x), __float2half(y));
    return *reinterpret_cast<u32*>(&hp);
}

__device__ __forceinline__ void mma16816(float* d, u32 a0, u32 a1, u32 a2, u32 a3,
                                         u32 b0, u32 b1) {
    asm("mma.sync.aligned.m16n8k16.row.col.f32.f16.f16.f32 "
        "{%0,%1,%2,%3}, {%4,%5,%6,%7}, {%8,%9}, {%0,%1,%2,%3};\n"
        : "+f"(d[0]), "+f"(d[1]), "+f"(d[2]), "+f"(d[3])
        : "r"(a0), "r"(a1), "r"(a2), "r"(a3), "r"(b0), "r"(b1));
}

__device__ __forceinline__ void ldsm4(u32* r, u32 saddr) {
    asm volatile(
        "ldmatrix.sync.aligned.m8n8.x4.shared.b16 {%0,%1,%2,%3}, [%4];"
        : "=r"(r[0]), "=r"(r[1]), "=r"(r[2]), "=r"(r[3]) : "r"(saddr));
}

__device__ __forceinline__ u32 smem_u32(const void* p) {
    return (u32)__cvta_generic_to_shared(p);
}

__device__ __forceinline__ void cp16(void* dst, const void* src) {
    u32 d = (u32)__cvta_generic_to_shared(dst);
    asm volatile("cp.async.cg.shared.global [%0], [%1], 16;\n" :: "r"(d), "l"(src));
}
__device__ __forceinline__ void cp_commit() { asm volatile("cp.async.commit_group;\n"); }
__device__ __forceinline__ void cp_wait1()  { asm volatile("cp.async.wait_group 1;\n"); }
__device__ __forceinline__ void cp_wait0()  { asm volatile("cp.async.wait_group 0;\n"); }

// ================================================================================
// Unified prep kernel
// ================================================================================
__global__ __launch_bounds__(256) void prep_kernel(const float* __restrict__ X,
                                                   const float* __restrict__ Wq,
                                                   const float* __restrict__ Wk,
                                                   const float* __restrict__ Wv,
                                                   const float* __restrict__ Wo) {
    const int blk = blockIdx.x;
    if (blk < 16384) {
        int idx = blk * 256 + threadIdx.x;
        g_Xh[idx] = __float2half(X[idx]);
        return;
    }
    __shared__ float tile[32][33];
    const int tx = threadIdx.x & 31, ty = threadIdx.x >> 5;
    if (blk < 19456) {
        int r = blk - 16384;
        int x = r & 1, y = (r >> 1) & 31, z = r >> 6;
        int w = z >> 4, h = z & 15;
        const float* in = ((w == 0) ? Wq : (w == 1) ? Wk : Wv) + (size_t)h * EMB * HDIM;
        __half* oh = g_Wh + (size_t)w * 1048576 + (size_t)h * 64 * 1024;
        int e0 = y * 32, d0 = x * 32;
        for (int i = ty; i < 32; i += 8)
            tile[i][tx] = in[(size_t)(e0 + i) * HDIM + d0 + tx];
        __syncthreads();
        for (int i = ty; i < 32; i += 8)
            oh[(size_t)(d0 + i) * 1024 + e0 + tx] = __float2half(tile[tx][i]);
    } else {
        int r = blk - 19456;
        int x = r & 31, y = r >> 5;
        __half* oh = g_Wh + 3u * 1048576;
        int k0 = y * 32, n0 = x * 32;
        for (int i = ty; i < 32; i += 8)
            tile[i][tx] = Wo[(size_t)(k0 + i) * 1024 + n0 + tx];
        __syncthreads();
        for (int i = ty; i < 32; i += 8)
            oh[(size_t)(n0 + i) * 1024 + k0 + tx] = __float2half(tile[tx][i]);
    }
}

// ================================================================================
// Plain fp16 GEMM, BK=64, 2-stage cp.async pipeline.
// Stage layout (halfs): A[128][72] @0, B[128][72] @9216; 18432 elems/stage.
// 16 mainloop iterations; 32 MMAs per warp between syncs.
// ================================================================================
#define GEMM_SMEM 73728
#define ST_ELEMS  18432
#define ST_BYTES  36864
#define G_STRIDE  72

__global__ __launch_bounds__(256, 2) void gemm_kernel(int mode,
                                                      const float* __restrict__ gate,
                                                      float* __restrict__ out) {
    extern __shared__ __half sm[];
    if (mode < 0) mode = blockIdx.z;

    const int bm = blockIdx.x * 128;
    const int bn = blockIdx.y * 128;

    const __half *pAh, *pBh;
    if (mode < 3) {
        pAh = g_Xh;
        pBh = g_Wh + (size_t)mode * 1048576;
    } else {
        pAh = g_Ch;
        pBh = g_Wh + 3u * 1048576;
    }

    const int tid = threadIdx.x;
    const int lane = tid & 31, warp = tid >> 5;
    const int wr = warp & 3, wc = warp >> 2;
    const int g = lane >> 2, c = lane & 3;

    const int lrow = tid >> 1;               // 0..127
    const int lseg0 = (tid & 1) * 4;         // 0 or 4 (4 segs of 8 halfs each)

    const u32 smb = smem_u32(sm);
    const int lrA = lane & 15, lcA = (lane >> 4) << 3;
    const int lrB = (lane & 7) | ((lane >> 4) << 3);
    const int lcB = ((lane >> 3) & 1) << 3;
    const u32 offA = smb + (u32)(((wr * 32 + lrA) * G_STRIDE + lcA) * 2);
    const u32 offB = smb + (u32)(ST_ELEMS / 2 * 2 * 0) + 18432u + (u32)(((wc * 64 + lrB) * G_STRIDE + lcB) * 2);

    float acc[2][8][4];
#pragma unroll
    for (int mt = 0; mt < 2; mt++)
#pragma unroll
        for (int j = 0; j < 8; j++)
#pragma unroll
            for (int q = 0; q < 4; q++) acc[mt][j][q] = 0.0f;

    #define G_FILL(ST) do {                                                        \
        __half* base_ = sm + ((ST) & 1) * ST_ELEMS;                                \
        const int k0_ = (ST) * 64;                                                 \
        _Pragma("unroll")                                                          \
        for (int i_ = 0; i_ < 4; i_++) {                                           \
            int seg_ = lseg0 + i_;                                                 \
            int off_ = lrow * G_STRIDE + seg_ * 8;                                 \
            cp16(base_ + off_, pAh + (size_t)(bm + lrow) * 1024 + k0_ + seg_ * 8); \
            cp16(base_ + 9216 + off_, pBh + (size_t)(bn + lrow) * 1024 + k0_ + seg_ * 8);\
        }                                                                          \
        cp_commit();                                                               \
    } while (0)

    G_FILL(0);
    G_FILL(1);

    for (int it = 0; it < 16; it++) {
        const int cur = it & 1;
        if (it + 1 < 16) cp_wait1(); else cp_wait0();
        __syncthreads();

        const u32 stb = (u32)(cur * ST_BYTES);
#pragma unroll
        for (int kk = 0; kk < 4; kk++) {
            u32 aH[2][4];
#pragma unroll
            for (int mt = 0; mt < 2; mt++)
                ldsm4(aH[mt], offA + stb + mt * (16 * G_STRIDE * 2) + kk * 32);
#pragma unroll
            for (int jj = 0; jj < 4; jj++) {
                u32 bH[4];
                ldsm4(bH, offB + stb + jj * (16 * G_STRIDE * 2) + kk * 32);
#pragma unroll
                for (int mt = 0; mt < 2; mt++) {
                    mma16816(acc[mt][2 * jj],     aH[mt][0], aH[mt][1], aH[mt][2], aH[mt][3], bH[0], bH[1]);
                    mma16816(acc[mt][2 * jj + 1], aH[mt][0], aH[mt][1], aH[mt][2], aH[mt][3], bH[2], bH[3]);
                }
            }
        }
        __syncthreads();
        if (it + 2 < 16) G_FILL(it + 2);
    }

    // ---------------- epilogues ----------------
    if (mode == 3) {
        int cnt = 0;
#pragma unroll
        for (int i = 0; i < NHEAD; i++) cnt += (gate[i] > GATE_EPS) ? 1 : 0;
        float scale = (cnt > 0) ? 1.0f / fmaxf(1.0f, (float)cnt / (float)NHEAD) : 1.0f;
#pragma unroll
        for (int mt = 0; mt < 2; mt++) {
            int row = bm + wr * 32 + mt * 16 + g;
#pragma unroll
            for (int j = 0; j < 8; j++) {
                int n0 = bn + wc * 64 + j * 8 + 2 * c;
                float2 v0 = make_float2(acc[mt][j][0] * scale, acc[mt][j][1] * scale);
                float2 v1 = make_float2(acc[mt][j][2] * scale, acc[mt][j][3] * scale);
                *(float2*)&out[(size_t)row * 1024 + n0] = v0;
                *(float2*)&out[(size_t)(row + 8) * 1024 + n0] = v1;
            }
        }
    } else if (mode == 2) {
#pragma unroll
        for (int mt = 0; mt < 2; mt++) {
            int row = bm + wr * 32 + mt * 16 + g;
            int b = row >> 11, s = row & (SEQ - 1);
#pragma unroll
            for (int j = 0; j < 8; j++) {
                int n0 = bn + wc * 64 + j * 8 + 2 * c;
                int h = n0 >> 6, d = n0 & 63;
                size_t vb = (size_t)(b * 16 + h) * 64;
                g_Vh[(vb + d) * 2048 + s]         = __float2half(acc[mt][j][0]);
                g_Vh[(vb + d + 1) * 2048 + s]     = __float2half(acc[mt][j][1]);
                g_Vh[(vb + d) * 2048 + s + 8]     = __float2half(acc[mt][j][2]);
                g_Vh[(vb + d + 1) * 2048 + s + 8] = __float2half(acc[mt][j][3]);
            }
        }
    } else {
        __half* dst = (mode == 0) ? g_Qh : g_Kh;
#pragma unroll
        for (int mt = 0; mt < 2; mt++) {
            int row = bm + wr * 32 + mt * 16 + g;
            int b = row >> 11, s = row & (SEQ - 1);
#pragma unroll
            for (int j = 0; j < 8; j++) {
                int n0 = bn + wc * 64 + j * 8 + 2 * c;
                int h = n0 >> 6, d = n0 & 63;
                size_t base = (((size_t)(b * 16 + h)) * SEQ + s) * 64 + d;
                *(u32*)&dst[base] = pack_half2(acc[mt][j][0], acc[mt][j][1]);
                *(u32*)&dst[base + 8 * 64] = pack_half2(acc[mt][j][2], acc[mt][j][3]);
            }
        }
    }
}

// ================================================================================
// Fused flash attention, plain fp16; 2 CTAs/SM.  (unchanged from R13)
// ================================================================================
#define QK_STRIDE 72
#define V_STRIDE  136
#define F_KH_B 18432
#define F_VH_B 55296
#define F_MK_B 90112
#define FLASH_SMEM 91136

__global__ __launch_bounds__(256, 2) void flash_kernel(const float* __restrict__ mask,
                                                       const float* __restrict__ gate) {
    extern __shared__ char smraw[];
    __half* S = (__half*)smraw;
    float* maskS = (float*)(smraw + F_MK_B);

    const int bm = blockIdx.x * 128;
    const int bh = blockIdx.y;
    const int b = bh >> 4, h = bh & 15;

    const int tid = threadIdx.x;
    const int lane = tid & 31, warp = tid >> 5;
    const int g = lane >> 2, c = lane & 3;
    const int mr = warp * 16;

    const u32 sb = smem_u32(smraw);
    const int lrA = lane & 15, lcA = (lane >> 4) << 3;
    const int lrB = (lane & 7) | ((lane >> 4) << 3);
    const int lcB = ((lane >> 3) & 1) << 3;
    const u32 qAddrH = sb + (u32)((mr + lrA) * 144 + lcA * 2);
    const u32 kAddrH = sb + F_KH_B + (u32)(lrB * 144 + lcB * 2);
    const u32 vAddrH = sb + F_VH_B + (u32)(lrB * 272 + lcB * 2);

    {
        const size_t qbase = ((size_t)bh * SEQ + bm) * 64;
#pragma unroll
        for (int i = 0; i < 4; i++) {
            int idx = tid + i * 256;
            int row = idx >> 3, seg = idx & 7;
            cp16(S + row * QK_STRIDE + seg * 8, g_Qh + qbase + (size_t)row * 64 + seg * 8);
        }
        const size_t kbase = (size_t)bh * SEQ * 64;
#pragma unroll
        for (int i = 0; i < 4; i++) {
            int idx = tid + i * 256;
            int row = idx >> 3, seg = idx & 7;
            cp16(S + 9216 + row * QK_STRIDE + seg * 8, g_Kh + kbase + (size_t)row * 64 + seg * 8);
        }
        const size_t vbase = (size_t)bh * 64 * 2048;
#pragma unroll
        for (int i = 0; i < 4; i++) {
            int idx = tid + i * 256;
            int d = idx >> 4, seg = idx & 15;
            cp16(S + 27648 + d * V_STRIDE + seg * 8, g_Vh + vbase + (size_t)d * 2048 + seg * 8);
        }
        if (tid < 32) cp16(maskS + tid * 4, mask + b * SEQ + tid * 4);
        cp_commit();
    }
    cp_wait0();
    __syncthreads();

    u32 qH[4][4];
#pragma unroll
    for (int kk = 0; kk < 4; kk++)
        ldsm4(qH[kk], qAddrH + kk * 32);

    float o[8][4];
#pragma unroll
    for (int j = 0; j < 8; j++)
#pragma unroll
        for (int q = 0; q < 4; q++) o[j][q] = 0.0f;
    float m0 = -1e30f, m1 = -1e30f, l0 = 0.0f, l1 = 0.0f;

    for (int it = 0; it < 16; it++) {
        const int cur = it & 1;
        if (it + 1 < 16) {
            const int st = cur ^ 1;
            const int t0 = (it + 1) * 128;
            const size_t kbase = ((size_t)bh * SEQ + t0) * 64;
#pragma unroll
            for (int i = 0; i < 4; i++) {
                int idx = tid + i * 256;
                int row = idx >> 3, seg = idx & 7;
                cp16(S + 9216 + st * 9216 + row * QK_STRIDE + seg * 8,
                     g_Kh + kbase + (size_t)row * 64 + seg * 8);
            }
            const size_t vbase = (size_t)bh * 64 * 2048 + t0;
#pragma unroll
            for (int i = 0; i < 4; i++) {
                int idx = tid + i * 256;
                int d = idx >> 4, seg = idx & 15;
                cp16(S + 27648 + st * 8704 + d * V_STRIDE + seg * 8,
                     g_Vh + vbase + (size_t)d * 2048 + seg * 8);
            }
            if (tid < 32) cp16(maskS + st * 128 + tid * 4, mask + b * SEQ + t0 + tid * 4);
            cp_commit();
            cp_wait1();
        } else {
            cp_wait0();
        }
        __syncthreads();

        const u32 kStH = kAddrH + (u32)(cur * 18432);
        const u32 vStH = vAddrH + (u32)(cur * 17408);
        const float* mk = maskS + cur * 128;

        float s[16][4];
#pragma unroll
        for (int j = 0; j < 16; j++)
#pragma unroll
            for (int q = 0; q < 4; q++) s[j][q] = 0.0f;

#pragma unroll
        for (int kk = 0; kk < 4; kk++) {
#pragma unroll
            for (int jj = 0; jj < 8; jj += 2) {
                u32 kh0[4], kh1[4];
                ldsm4(kh0, kStH + jj * 2304 + kk * 32);
                ldsm4(kh1, kStH + (jj + 1) * 2304 + kk * 32);
                mma16816(s[2 * jj],     qH[kk][0], qH[kk][1], qH[kk][2], qH[kk][3], kh0[0], kh0[1]);
                mma16816(s[2 * jj + 1], qH[kk][0], qH[kk][1], qH[kk][2], qH[kk][3], kh0[2], kh0[3]);
                mma16816(s[2 * jj + 2], qH[kk][0], qH[kk][1], qH[kk][2], qH[kk][3], kh1[0], kh1[1]);
                mma16816(s[2 * jj + 3], qH[kk][0], qH[kk][1], qH[kk][2], qH[kk][3], kh1[2], kh1[3]);
            }
        }

#pragma unroll
        for (int j = 0; j < 16; j++) {
            float mk0 = mk[j * 8 + 2 * c];
            float mk1 = mk[j * 8 + 2 * c + 1];
            s[j][0] = s[j][0] * 0.125f + mk0;
            s[j][1] = s[j][1] * 0.125f + mk1;
            s[j][2] = s[j][2] * 0.125f + mk0;
            s[j][3] = s[j][3] * 0.125f + mk1;
        }

        float mt0 = -1e30f, mt1 = -1e30f;
#pragma unroll
        for (int j = 0; j < 16; j++) {
            mt0 = fmaxf(mt0, fmaxf(s[j][0], s[j][1]));
            mt1 = fmaxf(mt1, fmaxf(s[j][2], s[j][3]));
        }
        mt0 = fmaxf(mt0, __shfl_xor_sync(0xffffffffu, mt0, 1));
        mt0 = fmaxf(mt0, __shfl_xor_sync(0xffffffffu, mt0, 2));
        mt1 = fmaxf(mt1, __shfl_xor_sync(0xffffffffu, mt1, 1));
        mt1 = fmaxf(mt1, __shfl_xor_sync(0xffffffffu, mt1, 2));
        float mn0 = fmaxf(m0, mt0), mn1 = fmaxf(m1, mt1);
        float al0 = __expf(m0 - mn0), al1 = __expf(m1 - mn1);
        m0 = mn0; m1 = mn1;

        float rs0 = 0.0f, rs1 = 0.0f;
#pragma unroll
        for (int j = 0; j < 16; j++) {
            s[j][0] = __expf(s[j][0] - mn0); rs0 += s[j][0];
            s[j][1] = __expf(s[j][1] - mn0); rs0 += s[j][1];
            s[j][2] = __expf(s[j][2] - mn1); rs1 += s[j][2];
            s[j][3] = __expf(s[j][3] - mn1); rs1 += s[j][3];
        }
        rs0 += __shfl_xor_sync(0xffffffffu, rs0, 1);
        rs0 += __shfl_xor_sync(0xffffffffu, rs0, 2);
        rs1 += __shfl_xor_sync(0xffffffffu, rs1, 1);
        rs1 += __shfl_xor_sync(0xffffffffu, rs1, 2);
        l0 = l0 * al0 + rs0;
        l1 = l1 * al1 + rs1;
#pragma unroll
        for (int j = 0; j < 8; j++) {
            o[j][0] *= al0; o[j][1] *= al0;
            o[j][2] *= al1; o[j][3] *= al1;
        }

#pragma unroll
        for (int kk = 0; kk < 8; kk++) {
            u32 pa0 = pack_half2(s[2 * kk][0], s[2 * kk][1]);
            u32 pa1 = pack_half2(s[2 * kk][2], s[2 * kk][3]);
            u32 pa2 = pack_half2(s[2 * kk + 1][0], s[2 * kk + 1][1]);
            u32 pa3 = pack_half2(s[2 * kk + 1][2], s[2 * kk + 1][3]);
#pragma unroll
            for (int jj = 0; jj < 4; jj += 2) {
                u32 vh0[4], vh1[4];
                ldsm4(vh0, vStH + jj * 4352 + kk * 32);
                ldsm4(vh1, vStH + (jj + 1) * 4352 + kk * 32);
                mma16816(o[2 * jj],     pa0, pa1, pa2, pa3, vh0[0], vh0[1]);
                mma16816(o[2 * jj + 1], pa0, pa1, pa2, pa3, vh0[2], vh0[3]);
                mma16816(o[2 * jj + 2], pa0, pa1, pa2, pa3, vh1[0], vh1[1]);
                mma16816(o[2 * jj + 3], pa0, pa1, pa2, pa3, vh1[2], vh1[3]);
            }
        }
        __syncthreads();
    }

    float gv = gate[h];
    float eff = (gv >= GATE_EPS) ? gv : 0.0f;
    float inv0 = eff / l0, inv1 = eff / l1;
    int row0 = bm + mr + g;
#pragma unroll
    for (int j = 0; j < 8; j++) {
        int e0 = h * 64 + j * 8 + 2 * c;
        size_t base0 = ((size_t)b * SEQ + row0) * 1024 + e0;
        size_t base1 = ((size_t)b * SEQ + row0 + 8) * 1024 + e0;
        *(u32*)&g_Ch[base0] = pack_half2(o[j][0] * inv0, o[j][1] * inv0);
        *(u32*)&g_Ch[base1] = pack_half2(o[j][2] * inv1, o[j][3] * inv1);
    }
}

// ================================================================================
extern "C" void kernel_launch(void* const* d_in, const int* in_sizes, int n_in,
                              void* d_out, int out_size) {
    const float* X    = (const float*)d_in[0];
    const float* mask = (const float*)d_in[1];
    const float* Wq   = (const float*)d_in[2];
    const float* Wk   = (const float*)d_in[3];
    const float* Wv   = (const float*)d_in[4];
    const float* Wo   = (const float*)d_in[5];
    const float* gate = (const float*)d_in[6];
    float* out = (float*)d_out;

    cudaFuncSetAttribute(gemm_kernel, cudaFuncAttributeMaxDynamicSharedMemorySize, GEMM_SMEM);
    cudaFuncSetAttribute(flash_kernel, cudaFuncAttributeMaxDynamicSharedMemorySize, FLASH_SMEM);

    prep_kernel<<<20480, 256>>>(X, Wq, Wk, Wv, Wo);
    gemm_kernel<<<dim3(32, 8, 3), 256, GEMM_SMEM>>>(-1, gate, out);   // QKV
    flash_kernel<<<dim3(16, 32), 256, FLASH_SMEM>>>(mask, gate);
    gemm_kernel<<<dim3(32, 8, 1), 256, GEMM_SMEM>>>(3, gate, out);    // O proj
}

// round 15
// speedup vs baseline: 1.0870x; 1.0870x over previous
#include <cuda_runtime.h>
#include <cuda_fp16.h>
#include <math.h>

#define BATCH 2
#define NHEAD 16
#define SEQ   2048
#define EMB   1024
#define HDIM  64
#define GATE_EPS 1e-4f
#define LOG2E 1.44269504088896340736f

typedef unsigned int u32;

// ------------------ scratch (all fp16 hi-only) ------------------
__device__ __half g_Xh[4096 * 1024];
__device__ __half g_Wh[4 * 1024 * 1024];
__device__ __half g_Qh[32 * 2048 * 64];
__device__ __half g_Kh[32 * 2048 * 64];
__device__ __half g_Vh[32 * 64 * 2048];
__device__ __half g_Ch[4096 * 1024];
__device__ float  g_maskSc[2 * 2048];     // mask * log2(e)

// ------------------------------- helpers ---------------------------------------
__device__ __forceinline__ u32 pack_half2(float x, float y) {
    __half2 hp = __halves2half2(__float2half(x), __float2half(y));
    return *reinterpret_cast<u32*>(&hp);
}

__device__ __forceinline__ void mma16816(float* d, u32 a0, u32 a1, u32 a2, u32 a3,
                                         u32 b0, u32 b1) {
    asm("mma.sync.aligned.m16n8k16.row.col.f32.f16.f16.f32 "
        "{%0,%1,%2,%3}, {%4,%5,%6,%7}, {%8,%9}, {%0,%1,%2,%3};\n"
        : "+f"(d[0]), "+f"(d[1]), "+f"(d[2]), "+f"(d[3])
        : "r"(a0), "r"(a1), "r"(a2), "r"(a3), "r"(b0), "r"(b1));
}

__device__ __forceinline__ void ldsm4(u32* r, u32 saddr) {
    asm volatile(
        "ldmatrix.sync.aligned.m8n8.x4.shared.b16 {%0,%1,%2,%3}, [%4];"
        : "=r"(r[0]), "=r"(r[1]), "=r"(r[2]), "=r"(r[3]) : "r"(saddr));
}

__device__ __forceinline__ u32 smem_u32(const void* p) {
    return (u32)__cvta_generic_to_shared(p);
}

__device__ __forceinline__ void cp16(void* dst, const void* src) {
    u32 d = (u32)__cvta_generic_to_shared(dst);
    asm volatile("cp.async.cg.shared.global [%0], [%1], 16;\n" :: "r"(d), "l"(src));
}
__device__ __forceinline__ void cp_commit() { asm volatile("cp.async.commit_group;\n"); }
__device__ __forceinline__ void cp_wait2()  { asm volatile("cp.async.wait_group 2;\n"); }
__device__ __forceinline__ void cp_wait1()  { asm volatile("cp.async.wait_group 1;\n"); }
__device__ __forceinline__ void cp_wait0()  { asm volatile("cp.async.wait_group 0;\n"); }

// ================================================================================
// Unified prep kernel (single launch):
//   blocks [0, 4096)      : X fp32 -> fp16, float4-vectorized (4 elems/thread)
//   blocks [4096, 7168)   : transpose Wq/Wk/Wv per head [E][D] -> [D][E]
//   blocks [7168, 8192)   : transpose Wo [k][n] -> [n][k]
//   blocks [8192, 8208)   : mask * log2(e)
// ================================================================================
__global__ __launch_bounds__(256) void prep_kernel(const float* __restrict__ X,
                                                   const float* __restrict__ Wq,
                                                   const float* __restrict__ Wk,
                                                   const float* __restrict__ Wv,
                                                   const float* __restrict__ Wo,
                                                   const float* __restrict__ mask) {
    const int blk = blockIdx.x;
    if (blk < 4096) {
        int idx = blk * 1024 + threadIdx.x * 4;
        float4 v = *(const float4*)&X[idx];
        *(u32*)&g_Xh[idx]     = pack_half2(v.x, v.y);
        *(u32*)&g_Xh[idx + 2] = pack_half2(v.z, v.w);
        return;
    }
    if (blk >= 8192) {
        int idx = (blk - 8192) * 256 + threadIdx.x;
        g_maskSc[idx] = mask[idx] * LOG2E;
        return;
    }
    __shared__ float tile[32][33];
    const int tx = threadIdx.x & 31, ty = threadIdx.x >> 5;
    if (blk < 7168) {
        int r = blk - 4096;
        int x = r & 1, y = (r >> 1) & 31, z = r >> 6;
        int w = z >> 4, h = z & 15;
        const float* in = ((w == 0) ? Wq : (w == 1) ? Wk : Wv) + (size_t)h * EMB * HDIM;
        __half* oh = g_Wh + (size_t)w * 1048576 + (size_t)h * 64 * 1024;
        int e0 = y * 32, d0 = x * 32;
        for (int i = ty; i < 32; i += 8)
            tile[i][tx] = in[(size_t)(e0 + i) * HDIM + d0 + tx];
        __syncthreads();
        for (int i = ty; i < 32; i += 8)
            oh[(size_t)(d0 + i) * 1024 + e0 + tx] = __float2half(tile[tx][i]);
    } else {
        int r = blk - 7168;
        int x = r & 31, y = r >> 5;
        __half* oh = g_Wh + 3u * 1048576;
        int k0 = y * 32, n0 = x * 32;
        for (int i = ty; i < 32; i += 8)
            tile[i][tx] = Wo[(size_t)(k0 + i) * 1024 + n0 + tx];
        __syncthreads();
        for (int i = ty; i < 32; i += 8)
            oh[(size_t)(n0 + i) * 1024 + k0 + tx] = __float2half(tile[tx][i]);
    }
}

// ================================================================================
// Plain fp16 GEMM, BK=32, 3-stage cp.async pipeline (R13 config).
// ================================================================================
#define GEMM_SMEM 61440
#define ST_STRIDE 10240
#define ST_BYTES  20480

__global__ __launch_bounds__(256, 2) void gemm_kernel(int mode,
                                                      const float* __restrict__ gate,
                                                      float* __restrict__ out) {
    extern __shared__ __half sm[];
    if (mode < 0) mode = blockIdx.z;

    const int bm = blockIdx.x * 128;
    const int bn = blockIdx.y * 128;

    const __half *pAh, *pBh;
    if (mode < 3) {
        pAh = g_Xh;
        pBh = g_Wh + (size_t)mode * 1048576;
    } else {
        pAh = g_Ch;
        pBh = g_Wh + 3u * 1048576;
    }

    const int tid = threadIdx.x;
    const int lane = tid & 31, warp = tid >> 5;
    const int wr = warp & 3, wc = warp >> 2;
    const int g = lane >> 2, c = lane & 3;

    const int lrow = tid >> 1;
    const int lseg0 = (tid & 1) * 2;

    const u32 smb = smem_u32(sm);
    const int lrA = lane & 15, lcA = (lane >> 4) << 3;
    const int lrB = (lane & 7) | ((lane >> 4) << 3);
    const int lcB = ((lane >> 3) & 1) << 3;
    const u32 offA = smb + (u32)(((wr * 32 + lrA) * 40 + lcA) * 2);
    const u32 offB = smb + 10240u + (u32)(((wc * 64 + lrB) * 40 + lcB) * 2);

    float acc[2][8][4];
#pragma unroll
    for (int mt = 0; mt < 2; mt++)
#pragma unroll
        for (int j = 0; j < 8; j++)
#pragma unroll
            for (int q = 0; q < 4; q++) acc[mt][j][q] = 0.0f;

    #define G_FILL(ST) do {                                                       \
        __half* base_ = sm + ((ST) % 3) * ST_STRIDE;                              \
        const int k0_ = (ST) * 32;                                                \
        _Pragma("unroll")                                                         \
        for (int i_ = 0; i_ < 2; i_++) {                                          \
            int seg_ = lseg0 + i_;                                                \
            int off_ = lrow * 40 + seg_ * 8;                                      \
            cp16(base_ + off_, pAh + (size_t)(bm + lrow) * 1024 + k0_ + seg_ * 8);\
            cp16(base_ + 5120 + off_, pBh + (size_t)(bn + lrow) * 1024 + k0_ + seg_ * 8);\
        }                                                                         \
        cp_commit();                                                              \
    } while (0)

    G_FILL(0);
    G_FILL(1);
    G_FILL(2);

    for (int it = 0; it < 32; it++) {
        const int cur = it % 3;
        if (it + 3 < 32) { cp_wait2(); }
        else if (it + 1 < 32) { cp_wait1(); }
        else { cp_wait0(); }
        __syncthreads();

        const u32 stb = (u32)(cur * ST_BYTES);
#pragma unroll
        for (int kk = 0; kk < 2; kk++) {
            u32 aH[2][4];
#pragma unroll
            for (int mt = 0; mt < 2; mt++)
                ldsm4(aH[mt], offA + stb + mt * 1280 + kk * 32);
#pragma unroll
            for (int jj = 0; jj < 4; jj++) {
                u32 bH[4];
                ldsm4(bH, offB + stb + jj * 1280 + kk * 32);
#pragma unroll
                for (int mt = 0; mt < 2; mt++) {
                    mma16816(acc[mt][2 * jj],     aH[mt][0], aH[mt][1], aH[mt][2], aH[mt][3], bH[0], bH[1]);
                    mma16816(acc[mt][2 * jj + 1], aH[mt][0], aH[mt][1], aH[mt][2], aH[mt][3], bH[2], bH[3]);
                }
            }
        }
        __syncthreads();
        if (it + 3 < 32) G_FILL(it + 3);
    }

    // ---------------- epilogues ----------------
    if (mode == 3) {
        int cnt = 0;
#pragma unroll
        for (int i = 0; i < NHEAD; i++) cnt += (gate[i] > GATE_EPS) ? 1 : 0;
        float scale = (cnt > 0) ? 1.0f / fmaxf(1.0f, (float)cnt / (float)NHEAD) : 1.0f;
#pragma unroll
        for (int mt = 0; mt < 2; mt++) {
            int row = bm + wr * 32 + mt * 16 + g;
#pragma unroll
            for (int j = 0; j < 8; j++) {
                int n0 = bn + wc * 64 + j * 8 + 2 * c;
                float2 v0 = make_float2(acc[mt][j][0] * scale, acc[mt][j][1] * scale);
                float2 v1 = make_float2(acc[mt][j][2] * scale, acc[mt][j][3] * scale);
                *(float2*)&out[(size_t)row * 1024 + n0] = v0;
                *(float2*)&out[(size_t)(row + 8) * 1024 + n0] = v1;
            }
        }
    } else if (mode == 2) {
#pragma unroll
        for (int mt = 0; mt < 2; mt++) {
            int row = bm + wr * 32 + mt * 16 + g;
            int b = row >> 11, s = row & (SEQ - 1);
#pragma unroll
            for (int j = 0; j < 8; j++) {
                int n0 = bn + wc * 64 + j * 8 + 2 * c;
                int h = n0 >> 6, d = n0 & 63;
                size_t vb = (size_t)(b * 16 + h) * 64;
                g_Vh[(vb + d) * 2048 + s]         = __float2half(acc[mt][j][0]);
                g_Vh[(vb + d + 1) * 2048 + s]     = __float2half(acc[mt][j][1]);
                g_Vh[(vb + d) * 2048 + s + 8]     = __float2half(acc[mt][j][2]);
                g_Vh[(vb + d + 1) * 2048 + s + 8] = __float2half(acc[mt][j][3]);
            }
        }
    } else {
        __half* dst = (mode == 0) ? g_Qh : g_Kh;
#pragma unroll
        for (int mt = 0; mt < 2; mt++) {
            int row = bm + wr * 32 + mt * 16 + g;
            int b = row >> 11, s = row & (SEQ - 1);
#pragma unroll
            for (int j = 0; j < 8; j++) {
                int n0 = bn + wc * 64 + j * 8 + 2 * c;
                int h = n0 >> 6, d = n0 & 63;
                size_t base = (((size_t)(b * 16 + h)) * SEQ + s) * 64 + d;
                *(u32*)&dst[base] = pack_half2(acc[mt][j][0], acc[mt][j][1]);
                *(u32*)&dst[base + 8 * 64] = pack_half2(acc[mt][j][2], acc[mt][j][3]);
            }
        }
    }
}

// ================================================================================
// Fused flash attention, plain fp16, log2-domain softmax; 2 CTAs/SM.
// ================================================================================
#define QK_STRIDE 72
#define V_STRIDE  136
#define F_KH_B 18432
#define F_VH_B 55296
#define F_MK_B 90112
#define FLASH_SMEM 91136
#define SSCALE (0.125f * LOG2E)

__global__ __launch_bounds__(256, 2) void flash_kernel(const float* __restrict__ gate) {
    extern __shared__ char smraw[];
    __half* S = (__half*)smraw;
    float* maskS = (float*)(smraw + F_MK_B);

    const int bm = blockIdx.x * 128;
    const int bh = blockIdx.y;
    const int b = bh >> 4, h = bh & 15;

    const int tid = threadIdx.x;
    const int lane = tid & 31, warp = tid >> 5;
    const int g = lane >> 2, c = lane & 3;
    const int mr = warp * 16;

    const u32 sb = smem_u32(smraw);
    const int lrA = lane & 15, lcA = (lane >> 4) << 3;
    const int lrB = (lane & 7) | ((lane >> 4) << 3);
    const int lcB = ((lane >> 3) & 1) << 3;
    const u32 qAddrH = sb + (u32)((mr + lrA) * 144 + lcA * 2);
    const u32 kAddrH = sb + F_KH_B + (u32)(lrB * 144 + lcB * 2);
    const u32 vAddrH = sb + F_VH_B + (u32)(lrB * 272 + lcB * 2);

    {
        const size_t qbase = ((size_t)bh * SEQ + bm) * 64;
#pragma unroll
        for (int i = 0; i < 4; i++) {
            int idx = tid + i * 256;
            int row = idx >> 3, seg = idx & 7;
            cp16(S + row * QK_STRIDE + seg * 8, g_Qh + qbase + (size_t)row * 64 + seg * 8);
        }
        const size_t kbase = (size_t)bh * SEQ * 64;
#pragma unroll
        for (int i = 0; i < 4; i++) {
            int idx = tid + i * 256;
            int row = idx >> 3, seg = idx & 7;
            cp16(S + 9216 + row * QK_STRIDE + seg * 8, g_Kh + kbase + (size_t)row * 64 + seg * 8);
        }
        const size_t vbase = (size_t)bh * 64 * 2048;
#pragma unroll
        for (int i = 0; i < 4; i++) {
            int idx = tid + i * 256;
            int d = idx >> 4, seg = idx & 15;
            cp16(S + 27648 + d * V_STRIDE + seg * 8, g_Vh + vbase + (size_t)d * 2048 + seg * 8);
        }
        if (tid < 32) cp16(maskS + tid * 4, g_maskSc + b * SEQ + tid * 4);
        cp_commit();
    }
    cp_wait0();
    __syncthreads();

    u32 qH[4][4];
#pragma unroll
    for (int kk = 0; kk < 4; kk++)
        ldsm4(qH[kk], qAddrH + kk * 32);

    float o[8][4];
#pragma unroll
    for (int j = 0; j < 8; j++)
#pragma unroll
        for (int q = 0; q < 4; q++) o[j][q] = 0.0f;
    float m0 = -1e30f, m1 = -1e30f, l0 = 0.0f, l1 = 0.0f;

    for (int it = 0; it < 16; it++) {
        const int cur = it & 1;
        if (it + 1 < 16) {
            const int st = cur ^ 1;
            const int t0 = (it + 1) * 128;
            const size_t kbase = ((size_t)bh * SEQ + t0) * 64;
#pragma unroll
            for (int i = 0; i < 4; i++) {
                int idx = tid + i * 256;
                int row = idx >> 3, seg = idx & 7;
                cp16(S + 9216 + st * 9216 + row * QK_STRIDE + seg * 8,
                     g_Kh + kbase + (size_t)row * 64 + seg * 8);
            }
            const size_t vbase = (size_t)bh * 64 * 2048 + t0;
#pragma unroll
            for (int i = 0; i < 4; i++) {
                int idx = tid + i * 256;
                int d = idx >> 4, seg = idx & 15;
                cp16(S + 27648 + st * 8704 + d * V_STRIDE + seg * 8,
                     g_Vh + vbase + (size_t)d * 2048 + seg * 8);
            }
            if (tid < 32) cp16(maskS + st * 128 + tid * 4, g_maskSc + b * SEQ + t0 + tid * 4);
            cp_commit();
            cp_wait1();
        } else {
            cp_wait0();
        }
        __syncthreads();

        const u32 kStH = kAddrH + (u32)(cur * 18432);
        const u32 vStH = vAddrH + (u32)(cur * 17408);
        const float* mk = maskS + cur * 128;

        float s[16][4];
#pragma unroll
        for (int j = 0; j < 16; j++)
#pragma unroll
            for (int q = 0; q < 4; q++) s[j][q] = 0.0f;

#pragma unroll
        for (int kk = 0; kk < 4; kk++) {
#pragma unroll
            for (int jj = 0; jj < 8; jj += 2) {
                u32 kh0[4], kh1[4];
                ldsm4(kh0, kStH + jj * 2304 + kk * 32);
                ldsm4(kh1, kStH + (jj + 1) * 2304 + kk * 32);
                mma16816(s[2 * jj],     qH[kk][0], qH[kk][1], qH[kk][2], qH[kk][3], kh0[0], kh0[1]);
                mma16816(s[2 * jj + 1], qH[kk][0], qH[kk][1], qH[kk][2], qH[kk][3], kh0[2], kh0[3]);
                mma16816(s[2 * jj + 2], qH[kk][0], qH[kk][1], qH[kk][2], qH[kk][3], kh1[0], kh1[1]);
                mma16816(s[2 * jj + 3], qH[kk][0], qH[kk][1], qH[kk][2], qH[kk][3], kh1[2], kh1[3]);
            }
        }

        // log2-domain: s' = s * 0.125*log2e + mask*log2e
#pragma unroll
        for (int j = 0; j < 16; j++) {
            float mk0 = mk[j * 8 + 2 * c];
            float mk1 = mk[j * 8 + 2 * c + 1];
            s[j][0] = s[j][0] * SSCALE + mk0;
            s[j][1] = s[j][1] * SSCALE + mk1;
            s[j][2] = s[j][2] * SSCALE + mk0;
            s[j][3] = s[j][3] * SSCALE + mk1;
        }

        float mt0 = -1e30f, mt1 = -1e30f;
#pragma unroll
        for (int j = 0; j < 16; j++) {
            mt0 = fmaxf(mt0, fmaxf(s[j][0], s[j][1]));
            mt1 = fmaxf(mt1, fmaxf(s[j][2], s[j][3]));
        }
        mt0 = fmaxf(mt0, __shfl_xor_sync(0xffffffffu, mt0, 1));
        mt0 = fmaxf(mt0, __shfl_xor_sync(0xffffffffu, mt0, 2));
        mt1 = fmaxf(mt1, __shfl_xor_sync(0xffffffffu, mt1, 1));
        mt1 = fmaxf(mt1, __shfl_xor_sync(0xffffffffu, mt1, 2));
        float mn0 = fmaxf(m0, mt0), mn1 = fmaxf(m1, mt1);
        float al0 = exp2f(m0 - mn0), al1 = exp2f(m1 - mn1);
        m0 = mn0; m1 = mn1;

        float rs0 = 0.0f, rs1 = 0.0f;
#pragma unroll
        for (int j = 0; j < 16; j++) {
            s[j][0] = exp2f(s[j][0] - mn0); rs0 += s[j][0];
            s[j][1] = exp2f(s[j][1] - mn0); rs0 += s[j][1];
            s[j][2] = exp2f(s[j][2] - mn1); rs1 += s[j][2];
            s[j][3] = exp2f(s[j][3] - mn1); rs1 += s[j][3];
        }
        rs0 += __shfl_xor_sync(0xffffffffu, rs0, 1);
        rs0 += __shfl_xor_sync(0xffffffffu, rs0, 2);
        rs1 += __shfl_xor_sync(0xffffffffu, rs1, 1);
        rs1 += __shfl_xor_sync(0xffffffffu, rs1, 2);
        l0 = l0 * al0 + rs0;
        l1 = l1 * al1 + rs1;
#pragma unroll
        for (int j = 0; j < 8; j++) {
            o[j][0] *= al0; o[j][1] *= al0;
            o[j][2] *= al1; o[j][3] *= al1;
        }

#pragma unroll
        for (int kk = 0; kk < 8; kk++) {
            u32 pa0 = pack_half2(s[2 * kk][0], s[2 * kk][1]);
            u32 pa1 = pack_half2(s[2 * kk][2], s[2 * kk][3]);
            u32 pa2 = pack_half2(s[2 * kk + 1][0], s[2 * kk + 1][1]);
            u32 pa3 = pack_half2(s[2 * kk + 1][2], s[2 * kk + 1][3]);
#pragma unroll
            for (int jj = 0; jj < 4; jj += 2) {
                u32 vh0[4], vh1[4];
                ldsm4(vh0, vStH + jj * 4352 + kk * 32);
                ldsm4(vh1, vStH + (jj + 1) * 4352 + kk * 32);
                mma16816(o[2 * jj],     pa0, pa1, pa2, pa3, vh0[0], vh0[1]);
                mma16816(o[2 * jj + 1], pa0, pa1, pa2, pa3, vh0[2], vh0[3]);
                mma16816(o[2 * jj + 2], pa0, pa1, pa2, pa3, vh1[0], vh1[1]);
                mma16816(o[2 * jj + 3], pa0, pa1, pa2, pa3, vh1[2], vh1[3]);
            }
        }
        __syncthreads();
    }

    float gv = gate[h];
    float eff = (gv >= GATE_EPS) ? gv : 0.0f;
    float inv0 = eff / l0, inv1 = eff / l1;
    int row0 = bm + mr + g;
#pragma unroll
    for (int j = 0; j < 8; j++) {
        int e0 = h * 64 + j * 8 + 2 * c;
        size_t base0 = ((size_t)b * SEQ + row0) * 1024 + e0;
        size_t base1 = ((size_t)b * SEQ + row0 + 8) * 1024 + e0;
        *(u32*)&g_Ch[base0] = pack_half2(o[j][0] * inv0, o[j][1] * inv0);
        *(u32*)&g_Ch[base1] = pack_half2(o[j][2] * inv1, o[j][3] * inv1);
    }
}

// ================================================================================
extern "C" void kernel_launch(void* const* d_in, const int* in_sizes, int n_in,
                              void* d_out, int out_size) {
    const float* X    = (const float*)d_in[0];
    const float* mask = (const float*)d_in[1];
    const float* Wq   = (const float*)d_in[2];
    const float* Wk   = (const float*)d_in[3];
    const float* Wv   = (const float*)d_in[4];
    const float* Wo   = (const float*)d_in[5];
    const float* gate = (const float*)d_in[6];
    float* out = (float*)d_out;

    cudaFuncSetAttribute(gemm_kernel, cudaFuncAttributeMaxDynamicSharedMemorySize, GEMM_SMEM);
    cudaFuncSetAttribute(flash_kernel, cudaFuncAttributeMaxDynamicSharedMemorySize, FLASH_SMEM);

    prep_kernel<<<8208, 256>>>(X, Wq, Wk, Wv, Wo, mask);
    gemm_kernel<<<dim3(32, 8, 3), 256, GEMM_SMEM>>>(-1, gate, out);   // QKV
    flash_kernel<<<dim3(16, 32), 256, FLASH_SMEM>>>(gate);
    gemm_kernel<<<dim3(32, 8, 1), 256, GEMM_SMEM>>>(3, gate, out);    // O proj
}

// round 16
// speedup vs baseline: 1.1031x; 1.0148x over previous
#include <cuda_runtime.h>
#include <cuda_fp16.h>
#include <math.h>

#define BATCH 2
#define NHEAD 16
#define SEQ   2048
#define EMB   1024
#define HDIM  64
#define GATE_EPS 1e-4f
#define LOG2E 1.44269504088896340736f

typedef unsigned int u32;

// ------------------ scratch (all fp16 hi-only) ------------------
__device__ __half g_Xh[4096 * 1024];
__device__ __half g_Wh[4 * 1024 * 1024];
__device__ __half g_Qh[32 * 2048 * 64];
__device__ __half g_Kh[32 * 2048 * 64];
__device__ __half g_Vh[32 * 64 * 2048];
__device__ __half g_Ch[4096 * 1024];
__device__ float  g_maskSc[2 * 2048];     // mask * log2(e)

// ------------------------------- helpers ---------------------------------------
__device__ __forceinline__ u32 pack_half2(float x, float y) {
    __half2 hp = __halves2half2(__float2half(x), __float2half(y));
    return *reinterpret_cast<u32*>(&hp);
}

__device__ __forceinline__ void mma16816(float* d, u32 a0, u32 a1, u32 a2, u32 a3,
                                         u32 b0, u32 b1) {
    asm("mma.sync.aligned.m16n8k16.row.col.f32.f16.f16.f32 "
        "{%0,%1,%2,%3}, {%4,%5,%6,%7}, {%8,%9}, {%0,%1,%2,%3};\n"
        : "+f"(d[0]), "+f"(d[1]), "+f"(d[2]), "+f"(d[3])
        : "r"(a0), "r"(a1), "r"(a2), "r"(a3), "r"(b0), "r"(b1));
}

__device__ __forceinline__ void ldsm4(u32* r, u32 saddr) {
    asm volatile(
        "ldmatrix.sync.aligned.m8n8.x4.shared.b16 {%0,%1,%2,%3}, [%4];"
        : "=r"(r[0]), "=r"(r[1]), "=r"(r[2]), "=r"(r[3]) : "r"(saddr));
}

__device__ __forceinline__ u32 smem_u32(const void* p) {
    return (u32)__cvta_generic_to_shared(p);
}

__device__ __forceinline__ void cp16(void* dst, const void* src) {
    u32 d = (u32)__cvta_generic_to_shared(dst);
    asm volatile("cp.async.cg.shared.global [%0], [%1], 16;\n" :: "r"(d), "l"(src));
}
__device__ __forceinline__ void cp_commit() { asm volatile("cp.async.commit_group;\n"); }
__device__ __forceinline__ void cp_wait2()  { asm volatile("cp.async.wait_group 2;\n"); }
__device__ __forceinline__ void cp_wait1()  { asm volatile("cp.async.wait_group 1;\n"); }
__device__ __forceinline__ void cp_wait0()  { asm volatile("cp.async.wait_group 0;\n"); }

// ================================================================================
// Unified prep kernel
// ================================================================================
__global__ __launch_bounds__(256) void prep_kernel(const float* __restrict__ X,
                                                   const float* __restrict__ Wq,
                                                   const float* __restrict__ Wk,
                                                   const float* __restrict__ Wv,
                                                   const float* __restrict__ Wo,
                                                   const float* __restrict__ mask) {
    const int blk = blockIdx.x;
    if (blk < 4096) {
        int idx = blk * 1024 + threadIdx.x * 4;
        float4 v = *(const float4*)&X[idx];
        *(u32*)&g_Xh[idx]     = pack_half2(v.x, v.y);
        *(u32*)&g_Xh[idx + 2] = pack_half2(v.z, v.w);
        return;
    }
    if (blk >= 8192) {
        int idx = (blk - 8192) * 256 + threadIdx.x;
        g_maskSc[idx] = mask[idx] * LOG2E;
        return;
    }
    __shared__ float tile[32][33];
    const int tx = threadIdx.x & 31, ty = threadIdx.x >> 5;
    if (blk < 7168) {
        int r = blk - 4096;
        int x = r & 1, y = (r >> 1) & 31, z = r >> 6;
        int w = z >> 4, h = z & 15;
        const float* in = ((w == 0) ? Wq : (w == 1) ? Wk : Wv) + (size_t)h * EMB * HDIM;
        __half* oh = g_Wh + (size_t)w * 1048576 + (size_t)h * 64 * 1024;
        int e0 = y * 32, d0 = x * 32;
        for (int i = ty; i < 32; i += 8)
            tile[i][tx] = in[(size_t)(e0 + i) * HDIM + d0 + tx];
        __syncthreads();
        for (int i = ty; i < 32; i += 8)
            oh[(size_t)(d0 + i) * 1024 + e0 + tx] = __float2half(tile[tx][i]);
    } else {
        int r = blk - 7168;
        int x = r & 31, y = r >> 5;
        __half* oh = g_Wh + 3u * 1048576;
        int k0 = y * 32, n0 = x * 32;
        for (int i = ty; i < 32; i += 8)
            tile[i][tx] = Wo[(size_t)(k0 + i) * 1024 + n0 + tx];
        __syncthreads();
        for (int i = ty; i < 32; i += 8)
            oh[(size_t)(n0 + i) * 1024 + k0 + tx] = __float2half(tile[tx][i]);
    }
}

// ================================================================================
// Plain fp16 GEMM, BK=32, 4-stage cp.async pipeline, ONE barrier per iteration.
// Fill for stage it+3 reuses buffer (it-1)%4, whose readers are ordered by the
// top-of-loop barrier -> trailing barrier deleted.
// ================================================================================
#define GEMM_SMEM 81920
#define ST_STRIDE 10240
#define ST_BYTES  20480

__global__ __launch_bounds__(256, 2) void gemm_kernel(int mode,
                                                      const float* __restrict__ gate,
                                                      float* __restrict__ out) {
    extern __shared__ __half sm[];
    if (mode < 0) mode = blockIdx.z;

    const int bm = blockIdx.x * 128;
    const int bn = blockIdx.y * 128;

    const __half *pAh, *pBh;
    if (mode < 3) {
        pAh = g_Xh;
        pBh = g_Wh + (size_t)mode * 1048576;
    } else {
        pAh = g_Ch;
        pBh = g_Wh + 3u * 1048576;
    }

    const int tid = threadIdx.x;
    const int lane = tid & 31, warp = tid >> 5;
    const int wr = warp & 3, wc = warp >> 2;
    const int g = lane >> 2, c = lane & 3;

    const int lrow = tid >> 1;
    const int lseg0 = (tid & 1) * 2;

    const u32 smb = smem_u32(sm);
    const int lrA = lane & 15, lcA = (lane >> 4) << 3;
    const int lrB = (lane & 7) | ((lane >> 4) << 3);
    const int lcB = ((lane >> 3) & 1) << 3;
    const u32 offA = smb + (u32)(((wr * 32 + lrA) * 40 + lcA) * 2);
    const u32 offB = smb + 10240u + (u32)(((wc * 64 + lrB) * 40 + lcB) * 2);

    float acc[2][8][4];
#pragma unroll
    for (int mt = 0; mt < 2; mt++)
#pragma unroll
        for (int j = 0; j < 8; j++)
#pragma unroll
            for (int q = 0; q < 4; q++) acc[mt][j][q] = 0.0f;

    #define G_FILL(ST) do {                                                       \
        __half* base_ = sm + ((ST) & 3) * ST_STRIDE;                              \
        const int k0_ = (ST) * 32;                                                \
        _Pragma("unroll")                                                         \
        for (int i_ = 0; i_ < 2; i_++) {                                          \
            int seg_ = lseg0 + i_;                                                \
            int off_ = lrow * 40 + seg_ * 8;                                      \
            cp16(base_ + off_, pAh + (size_t)(bm + lrow) * 1024 + k0_ + seg_ * 8);\
            cp16(base_ + 5120 + off_, pBh + (size_t)(bn + lrow) * 1024 + k0_ + seg_ * 8);\
        }                                                                         \
        cp_commit();                                                              \
    } while (0)

    G_FILL(0);
    G_FILL(1);
    G_FILL(2);

    for (int it = 0; it < 32; it++) {
        const int cur = it & 3;
        if (it <= 29)      cp_wait2();
        else if (it == 30) cp_wait1();
        else               cp_wait0();
        __syncthreads();

        if (it + 3 < 32) G_FILL(it + 3);

        const u32 stb = (u32)(cur * ST_BYTES);
#pragma unroll
        for (int kk = 0; kk < 2; kk++) {
            u32 aH[2][4];
#pragma unroll
            for (int mt = 0; mt < 2; mt++)
                ldsm4(aH[mt], offA + stb + mt * 1280 + kk * 32);
#pragma unroll
            for (int jj = 0; jj < 4; jj++) {
                u32 bH[4];
                ldsm4(bH, offB + stb + jj * 1280 + kk * 32);
#pragma unroll
                for (int mt = 0; mt < 2; mt++) {
                    mma16816(acc[mt][2 * jj],     aH[mt][0], aH[mt][1], aH[mt][2], aH[mt][3], bH[0], bH[1]);
                    mma16816(acc[mt][2 * jj + 1], aH[mt][0], aH[mt][1], aH[mt][2], aH[mt][3], bH[2], bH[3]);
                }
            }
        }
    }
    __syncthreads();

    // ---------------- epilogues ----------------
    if (mode == 3) {
        int cnt = 0;
#pragma unroll
        for (int i = 0; i < NHEAD; i++) cnt += (gate[i] > GATE_EPS) ? 1 : 0;
        float scale = (cnt > 0) ? 1.0f / fmaxf(1.0f, (float)cnt / (float)NHEAD) : 1.0f;
#pragma unroll
        for (int mt = 0; mt < 2; mt++) {
            int row = bm + wr * 32 + mt * 16 + g;
#pragma unroll
            for (int j = 0; j < 8; j++) {
                int n0 = bn + wc * 64 + j * 8 + 2 * c;
                float2 v0 = make_float2(acc[mt][j][0] * scale, acc[mt][j][1] * scale);
                float2 v1 = make_float2(acc[mt][j][2] * scale, acc[mt][j][3] * scale);
                *(float2*)&out[(size_t)row * 1024 + n0] = v0;
                *(float2*)&out[(size_t)(row + 8) * 1024 + n0] = v1;
            }
        }
    } else if (mode == 2) {
#pragma unroll
        for (int mt = 0; mt < 2; mt++) {
            int row = bm + wr * 32 + mt * 16 + g;
            int b = row >> 11, s = row & (SEQ - 1);
#pragma unroll
            for (int j = 0; j < 8; j++) {
                int n0 = bn + wc * 64 + j * 8 + 2 * c;
                int h = n0 >> 6, d = n0 & 63;
                size_t vb = (size_t)(b * 16 + h) * 64;
                g_Vh[(vb + d) * 2048 + s]         = __float2half(acc[mt][j][0]);
                g_Vh[(vb + d + 1) * 2048 + s]     = __float2half(acc[mt][j][1]);
                g_Vh[(vb + d) * 2048 + s + 8]     = __float2half(acc[mt][j][2]);
                g_Vh[(vb + d + 1) * 2048 + s + 8] = __float2half(acc[mt][j][3]);
            }
        }
    } else {
        __half* dst = (mode == 0) ? g_Qh : g_Kh;
#pragma unroll
        for (int mt = 0; mt < 2; mt++) {
            int row = bm + wr * 32 + mt * 16 + g;
            int b = row >> 11, s = row & (SEQ - 1);
#pragma unroll
            for (int j = 0; j < 8; j++) {
                int n0 = bn + wc * 64 + j * 8 + 2 * c;
                int h = n0 >> 6, d = n0 & 63;
                size_t base = (((size_t)(b * 16 + h)) * SEQ + s) * 64 + d;
                *(u32*)&dst[base] = pack_half2(acc[mt][j][0], acc[mt][j][1]);
                *(u32*)&dst[base + 8 * 64] = pack_half2(acc[mt][j][2], acc[mt][j][3]);
            }
        }
    }
}

// ================================================================================
// Fused flash attention, plain fp16, log2-domain softmax; 2 CTAs/SM. (R15 config)
// ================================================================================
#define QK_STRIDE 72
#define V_STRIDE  136
#define F_KH_B 18432
#define F_VH_B 55296
#define F_MK_B 90112
#define FLASH_SMEM 91136
#define SSCALE (0.125f * LOG2E)

__global__ __launch_bounds__(256, 2) void flash_kernel(const float* __restrict__ gate) {
    extern __shared__ char smraw[];
    __half* S = (__half*)smraw;
    float* maskS = (float*)(smraw + F_MK_B);

    const int bm = blockIdx.x * 128;
    const int bh = blockIdx.y;
    const int b = bh >> 4, h = bh & 15;

    const int tid = threadIdx.x;
    const int lane = tid & 31, warp = tid >> 5;
    const int g = lane >> 2, c = lane & 3;
    const int mr = warp * 16;

    const u32 sb = smem_u32(smraw);
    const int lrA = lane & 15, lcA = (lane >> 4) << 3;
    const int lrB = (lane & 7) | ((lane >> 4) << 3);
    const int lcB = ((lane >> 3) & 1) << 3;
    const u32 qAddrH = sb + (u32)((mr + lrA) * 144 + lcA * 2);
    const u32 kAddrH = sb + F_KH_B + (u32)(lrB * 144 + lcB * 2);
    const u32 vAddrH = sb + F_VH_B + (u32)(lrB * 272 + lcB * 2);

    {
        const size_t qbase = ((size_t)bh * SEQ + bm) * 64;
#pragma unroll
        for (int i = 0; i < 4; i++) {
            int idx = tid + i * 256;
            int row = idx >> 3, seg = idx & 7;
            cp16(S + row * QK_STRIDE + seg * 8, g_Qh + qbase + (size_t)row * 64 + seg * 8);
        }
        const size_t kbase = (size_t)bh * SEQ * 64;
#pragma unroll
        for (int i = 0; i < 4; i++) {
            int idx = tid + i * 256;
            int row = idx >> 3, seg = idx & 7;
            cp16(S + 9216 + row * QK_STRIDE + seg * 8, g_Kh + kbase + (size_t)row * 64 + seg * 8);
        }
        const size_t vbase = (size_t)bh * 64 * 2048;
#pragma unroll
        for (int i = 0; i < 4; i++) {
            int idx = tid + i * 256;
            int d = idx >> 4, seg = idx & 15;
            cp16(S + 27648 + d * V_STRIDE + seg * 8, g_Vh + vbase + (size_t)d * 2048 + seg * 8);
        }
        if (tid < 32) cp16(maskS + tid * 4, g_maskSc + b * SEQ + tid * 4);
        cp_commit();
    }
    cp_wait0();
    __syncthreads();

    u32 qH[4][4];
#pragma unroll
    for (int kk = 0; kk < 4; kk++)
        ldsm4(qH[kk], qAddrH + kk * 32);

    float o[8][4];
#pragma unroll
    for (int j = 0; j < 8; j++)
#pragma unroll
        for (int q = 0; q < 4; q++) o[j][q] = 0.0f;
    float m0 = -1e30f, m1 = -1e30f, l0 = 0.0f, l1 = 0.0f;

    for (int it = 0; it < 16; it++) {
        const int cur = it & 1;
        if (it + 1 < 16) {
            const int st = cur ^ 1;
            const int t0 = (it + 1) * 128;
            const size_t kbase = ((size_t)bh * SEQ + t0) * 64;
#pragma unroll
            for (int i = 0; i < 4; i++) {
                int idx = tid + i * 256;
                int row = idx >> 3, seg = idx & 7;
                cp16(S + 9216 + st * 9216 + row * QK_STRIDE + seg * 8,
                     g_Kh + kbase + (size_t)row * 64 + seg * 8);
            }
            const size_t vbase = (size_t)bh * 64 * 2048 + t0;
#pragma unroll
            for (int i = 0; i < 4; i++) {
                int idx = tid + i * 256;
                int d = idx >> 4, seg = idx & 15;
                cp16(S + 27648 + st * 8704 + d * V_STRIDE + seg * 8,
                     g_Vh + vbase + (size_t)d * 2048 + seg * 8);
            }
            if (tid < 32) cp16(maskS + st * 128 + tid * 4, g_maskSc + b * SEQ + t0 + tid * 4);
            cp_commit();
            cp_wait1();
        } else {
            cp_wait0();
        }
        __syncthreads();

        const u32 kStH = kAddrH + (u32)(cur * 18432);
        const u32 vStH = vAddrH + (u32)(cur * 17408);
        const float* mk = maskS + cur * 128;

        float s[16][4];
#pragma unroll
        for (int j = 0; j < 16; j++)
#pragma unroll
            for (int q = 0; q < 4; q++) s[j][q] = 0.0f;

#pragma unroll
        for (int kk = 0; kk < 4; kk++) {
#pragma unroll
            for (int jj = 0; jj < 8; jj += 2) {
                u32 kh0[4], kh1[4];
                ldsm4(kh0, kStH + jj * 2304 + kk * 32);
                ldsm4(kh1, kStH + (jj + 1) * 2304 + kk * 32);
                mma16816(s[2 * jj],     qH[kk][0], qH[kk][1], qH[kk][2], qH[kk][3], kh0[0], kh0[1]);
                mma16816(s[2 * jj + 1], qH[kk][0], qH[kk][1], qH[kk][2], qH[kk][3], kh0[2], kh0[3]);
                mma16816(s[2 * jj + 2], qH[kk][0], qH[kk][1], qH[kk][2], qH[kk][3], kh1[0], kh1[1]);
                mma16816(s[2 * jj + 3], qH[kk][0], qH[kk][1], qH[kk][2], qH[kk][3], kh1[2], kh1[3]);
            }
        }

#pragma unroll
        for (int j = 0; j < 16; j++) {
            float mk0 = mk[j * 8 + 2 * c];
            float mk1 = mk[j * 8 + 2 * c + 1];
            s[j][0] = s[j][0] * SSCALE + mk0;
            s[j][1] = s[j][1] * SSCALE + mk1;
            s[j][2] = s[j][2] * SSCALE + mk0;
            s[j][3] = s[j][3] * SSCALE + mk1;
        }

        float mt0 = -1e30f, mt1 = -1e30f;
#pragma unroll
        for (int j = 0; j < 16; j++) {
            mt0 = fmaxf(mt0, fmaxf(s[j][0], s[j][1]));
            mt1 = fmaxf(mt1, fmaxf(s[j][2], s[j][3]));
        }
        mt0 = fmaxf(mt0, __shfl_xor_sync(0xffffffffu, mt0, 1));
        mt0 = fmaxf(mt0, __shfl_xor_sync(0xffffffffu, mt0, 2));
        mt1 = fmaxf(mt1, __shfl_xor_sync(0xffffffffu, mt1, 1));
        mt1 = fmaxf(mt1, __shfl_xor_sync(0xffffffffu, mt1, 2));
        float mn0 = fmaxf(m0, mt0), mn1 = fmaxf(m1, mt1);
        float al0 = exp2f(m0 - mn0), al1 = exp2f(m1 - mn1);
        m0 = mn0; m1 = mn1;

        float rs0 = 0.0f, rs1 = 0.0f;
#pragma unroll
        for (int j = 0; j < 16; j++) {
            s[j][0] = exp2f(s[j][0] - mn0); rs0 += s[j][0];
            s[j][1] = exp2f(s[j][1] - mn0); rs0 += s[j][1];
            s[j][2] = exp2f(s[j][2] - mn1); rs1 += s[j][2];
            s[j][3] = exp2f(s[j][3] - mn1); rs1 += s[j][3];
        }
        rs0 += __shfl_xor_sync(0xffffffffu, rs0, 1);
        rs0 += __shfl_xor_sync(0xffffffffu, rs0, 2);
        rs1 += __shfl_xor_sync(0xffffffffu, rs1, 1);
        rs1 += __shfl_xor_sync(0xffffffffu, rs1, 2);
        l0 = l0 * al0 + rs0;
        l1 = l1 * al1 + rs1;
#pragma unroll
        for (int j = 0; j < 8; j++) {
            o[j][0] *= al0; o[j][1] *= al0;
            o[j][2] *= al1; o[j][3] *= al1;
        }

#pragma unroll
        for (int kk = 0; kk < 8; kk++) {
            u32 pa0 = pack_half2(s[2 * kk][0], s[2 * kk][1]);
            u32 pa1 = pack_half2(s[2 * kk][2], s[2 * kk][3]);
            u32 pa2 = pack_half2(s[2 * kk + 1][0], s[2 * kk + 1][1]);
            u32 pa3 = pack_half2(s[2 * kk + 1][2], s[2 * kk + 1][3]);
#pragma unroll
            for (int jj = 0; jj < 4; jj += 2) {
                u32 vh0[4], vh1[4];
                ldsm4(vh0, vStH + jj * 4352 + kk * 32);
                ldsm4(vh1, vStH + (jj + 1) * 4352 + kk * 32);
                mma16816(o[2 * jj],     pa0, pa1, pa2, pa3, vh0[0], vh0[1]);
                mma16816(o[2 * jj + 1], pa0, pa1, pa2, pa3, vh0[2], vh0[3]);
                mma16816(o[2 * jj + 2], pa0, pa1, pa2, pa3, vh1[0], vh1[1]);
                mma16816(o[2 * jj + 3], pa0, pa1, pa2, pa3, vh1[2], vh1[3]);
            }
        }
        __syncthreads();
    }

    float gv = gate[h];
    float eff = (gv >= GATE_EPS) ? gv : 0.0f;
    float inv0 = eff / l0, inv1 = eff / l1;
    int row0 = bm + mr + g;
#pragma unroll
    for (int j = 0; j < 8; j++) {
        int e0 = h * 64 + j * 8 + 2 * c;
        size_t base0 = ((size_t)b * SEQ + row0) * 1024 + e0;
        size_t base1 = ((size_t)b * SEQ + row0 + 8) * 1024 + e0;
        *(u32*)&g_Ch[base0] = pack_half2(o[j][0] * inv0, o[j][1] * inv0);
        *(u32*)&g_Ch[base1] = pack_half2(o[j][2] * inv1, o[j][3] * inv1);
    }
}

// ================================================================================
extern "C" void kernel_launch(void* const* d_in, const int* in_sizes, int n_in,
                              void* d_out, int out_size) {
    const float* X    = (const float*)d_in[0];
    const float* mask = (const float*)d_in[1];
    const float* Wq   = (const float*)d_in[2];
    const float* Wk   = (const float*)d_in[3];
    const float* Wv   = (const float*)d_in[4];
    const float* Wo   = (const float*)d_in[5];
    const float* gate = (const float*)d_in[6];
    float* out = (float*)d_out;

    cudaFuncSetAttribute(gemm_kernel, cudaFuncAttributeMaxDynamicSharedMemorySize, GEMM_SMEM);
    cudaFuncSetAttribute(flash_kernel, cudaFuncAttributeMaxDynamicSharedMemorySize, FLASH_SMEM);

    prep_kernel<<<8208, 256>>>(X, Wq, Wk, Wv, Wo, mask);
    gemm_kernel<<<dim3(32, 8, 3), 256, GEMM_SMEM>>>(-1, gate, out);   // QKV
    flash_kernel<<<dim3(16, 32), 256, FLASH_SMEM>>>(gate);
    gemm_kernel<<<dim3(32, 8, 1), 256, GEMM_SMEM>>>(3, gate, out);    // O proj
}